// round 5
// baseline (speedup 1.0000x reference)
#include <cuda_runtime.h>
#include <cstdint>

#define B 4
#define N 1024
#define F 256
#define W 32            // 32 x u32 words per 1024-bit row
#define FULL 0xFFFFFFFFu

#define PACK_BLKS 512   // 512 blocks * 8 warps = 4096 rows
#define TOTAL_BLKS 2048 // extra 1536 blocks do the zero-fill
#define MAXK 344        // smem row-cache capacity in a_kernel (guarded fallback)
#define MAXL 128        // neighbor-list capacity in xp_kernel

// ---------------- scratch (device globals; no allocations allowed) ----------
__device__ unsigned g_bitsA [B][N][W];   // adj rows as bitmasks
__device__ unsigned g_bits1 [B][N][W];   // (adj + I) rows as bitmasks
__device__ uint2    g_excinc[B][N][W];   // {exc word, inc word} interleaved for select
__device__ int      g_rank  [B][N];      // stable sorted position of order[b][i]
__device__ int      g_inv   [B][N];      // inverse permutation: rank -> node
__device__ int      g_perm  [B][N];      // top_k permutation (stable)
__device__ int      g_K     [B];         // number of selected nodes

// Output layout (float32, concatenated):
#define OFF_X   0
#define OFF_P   (B*N*F)
#define OFF_A   (B*N*F + B*N*3)
#define OFF_M   (B*N*F + B*N*3 + B*N*N)
#define NZERO4  ((B*N*F + B*N*3 + B*N*N) / 4)

// ---------------- K0: pack adj rows into bitmasks + zero-fill outputs -------
__global__ void pack_zero_kernel(const float* __restrict__ adj, float* __restrict__ out) {
    if (blockIdx.x >= PACK_BLKS) {
        int zb = blockIdx.x - PACK_BLKS;
        float4 z = make_float4(0.f, 0.f, 0.f, 0.f);
        float4* o = (float4*)out;
        for (int i = zb * blockDim.x + threadIdx.x; i < NZERO4;
             i += (TOTAL_BLKS - PACK_BLKS) * blockDim.x)
            o[i] = z;
        return;
    }
    int warp = (blockIdx.x * blockDim.x + threadIdx.x) >> 5;   // 0..4095
    int lane = threadIdx.x & 31;
    int b = warp >> 10, i = warp & (N - 1);
    const float4* r4 = (const float4*)(adj + ((size_t)b * N + i) * N) + lane * 8;
    unsigned w = 0;
    #pragma unroll
    for (int j = 0; j < 8; ++j) {
        float4 v = r4[j];
        w |= (v.x != 0.f ? 1u : 0u) << (4 * j)
           | (v.y != 0.f ? 1u : 0u) << (4 * j + 1)
           | (v.z != 0.f ? 1u : 0u) << (4 * j + 2)
           | (v.w != 0.f ? 1u : 0u) << (4 * j + 3);
    }
    g_bitsA[b][i][lane] = w;
    unsigned m1 = w | ((lane == (i >> 5)) ? (1u << (i & 31)) : 0u);
    g_bits1[b][i][lane] = m1;
}

// ---------------- K1: included row i = OR of bitsA rows over k in bits1[i] --
__global__ void inc_kernel() {
    int warp = (blockIdx.x * blockDim.x + threadIdx.x) >> 5;
    int lane = threadIdx.x & 31;
    int b = warp >> 10, i = warp & (N - 1);
    unsigned myrow = g_bits1[b][i][lane];
    unsigned acc = 0;
    #pragma unroll 4
    for (int w = 0; w < W; ++w) {
        unsigned word = __shfl_sync(FULL, myrow, w);
        while (word) {
            int bit = __ffs(word) - 1;
            word &= word - 1;
            acc |= g_bitsA[b][w * 32 + bit][lane];
        }
    }
    g_excinc[b][i][lane] = make_uint2(myrow, acc);
}

// ---------------- K1b: stable rank of each node by order value --------------
// grid = B*8 blocks, 128 threads; thread handles node i = (blk%8)*128+tid
__global__ void rank_kernel(const float* __restrict__ order) {
    int b = blockIdx.x >> 3;
    int i = (blockIdx.x & 7) * 128 + threadIdx.x;
    __shared__ float so[N];
    for (int j = threadIdx.x; j < N; j += 128) so[j] = order[b * N + j];
    __syncthreads();
    float oi = so[i];
    int r = 0;
    const float4* s4 = (const float4*)so;
    #pragma unroll 8
    for (int j4 = 0; j4 < N / 4; ++j4) {
        float4 v = s4[j4];
        int j = j4 * 4;
        r += (v.x < oi) || (v.x == oi && (j + 0) < i);
        r += (v.y < oi) || (v.y == oi && (j + 1) < i);
        r += (v.z < oi) || (v.z == oi && (j + 2) < i);
        r += (v.w < oi) || (v.w == oi && (j + 3) < i);
    }
    g_rank[b][i] = r;
    g_inv[b][r] = i;
}

// ---------------- K2: serial greedy selection (1 warp per batch) ------------
__global__ void select_kernel(float* __restrict__ out_mask) {
    int b = blockIdx.x;
    int lane = threadIdx.x;
    __shared__ unsigned srank[N];
    __shared__ int      sinv [N];
    #pragma unroll
    for (int w = 0; w < W; ++w) {
        srank[w * 32 + lane] = (unsigned)g_rank[b][w * 32 + lane];
        sinv [w * 32 + lane] = g_inv[b][w * 32 + lane];
    }
    __syncwarp();

    unsigned av = FULL;            // node_mask is all-true
    unsigned sel = 0;
    int idx = sinv[0];             // argmin over all nodes = rank 0
    unsigned fr = ((idx >> 5) == lane) ? (1u << (idx & 31)) : 0u;

    int guard = 0;
    while (guard++ < 4 * N) {
        unsigned cur = ((idx >> 5) == lane) ? (1u << (idx & 31)) : 0u;
        sel |= cur;
        uint2 eg = g_excinc[b][idx][lane];     // one LDG.64: {exc, inc}
        av &= ~cur & ~eg.x;
        fr = (fr | eg.y) & av;
        if (!__any_sync(FULL, fr)) {           // frontier died -> restart on av
            fr = av;                           // (stale-idx pass is a no-op; skip it)
            if (!__any_sync(FULL, fr)) break;  // av empty -> done
        }
        // argmin by precomputed rank: per-lane scan + single REDUX
        unsigned m = fr, best = 0xFFFFFFFFu;
        while (m) {
            int t = __ffs(m) - 1;
            m &= m - 1;
            unsigned rk = srank[lane * 32 + t];
            if (rk < best) best = rk;
        }
        best = __reduce_min_sync(FULL, best);
        idx = sinv[best];
    }

    // stable top_k permutation: selected ascending, then unselected ascending
    int cnt = __popc(sel);
    int v = cnt;
    #pragma unroll
    for (int o = 1; o < 32; o <<= 1) {
        int n2 = __shfl_up_sync(FULL, v, o);
        if (lane >= o) v += n2;
    }
    int K = __shfl_sync(FULL, v, 31);
    int selpos = v - cnt;
    int unspos = K + (lane * 32 - selpos);
    #pragma unroll
    for (int i = 0; i < 32; ++i) {
        int node = lane * 32 + i;
        if ((sel >> i) & 1u) g_perm[b][selpos++] = node;
        else                 g_perm[b][unspos++] = node;
    }
    if (lane == 0) g_K[b] = K;
    #pragma unroll
    for (int w = 0; w < W; ++w) {
        int j = w * 32 + lane;
        out_mask[b * N + j] = (j < K) ? 1.0f : 0.0f;
    }
}

// ---------------- K3: pooled features x_p and pos_p (live rows only) --------
__global__ void xp_kernel(const float* __restrict__ x, const float* __restrict__ pos,
                          float* __restrict__ out_x, float* __restrict__ out_pos) {
    int b = blockIdx.y, k = blockIdx.x;
    if (k >= g_K[b]) return;                   // padding already zero-filled
    int f = threadIdx.x;                       // 256 threads == F
    __shared__ int spk, snn;
    __shared__ int list[MAXL];
    if (f == 0) spk = g_perm[b][k];
    __syncthreads();
    if (f < 32) {
        unsigned wd = g_bits1[b][spk][f];
        int c = __popc(wd);
        int v = c;
        #pragma unroll
        for (int o = 1; o < 32; o <<= 1) {
            int t = __shfl_up_sync(FULL, v, o);
            if (f >= o) v += t;
        }
        int p = v - c;
        while (wd) {
            int bt = __ffs(wd) - 1;
            wd &= wd - 1;
            list[p++] = f * 32 + bt;
        }
        if (f == 31) snn = v;
    }
    __syncthreads();
    int nn = snn;

    float acc = 0.0f;
    #pragma unroll 4
    for (int i = 0; i < nn; ++i)
        acc += x[((size_t)b * N + list[i]) * F + f];
    out_x[((size_t)b * N + k) * F + f] = acc;

    if (f < 3) {
        float p = 0.0f;
        for (int i = 0; i < nn; ++i)
            p += pos[((size_t)b * N + list[i]) * 3 + f];
        out_pos[((size_t)b * N + k) * 3 + f] = p / (float)nn;
    }
}

// ---------------- K4: coarsened adjacency, one block per batch --------------
__global__ void a_kernel(float* __restrict__ out_a) {
    int b = blockIdx.x;
    int K = g_K[b];
    __shared__ unsigned srows[MAXK][33];
    __shared__ int sperm[MAXK];
    int KC = K < MAXK ? K : MAXK;
    for (int j = threadIdx.x; j < KC; j += blockDim.x) sperm[j] = g_perm[b][j];
    __syncthreads();
    for (int t = threadIdx.x; t < KC * W; t += blockDim.x) {
        int j = t >> 5, w = t & 31;
        srows[j][w] = g_bitsA[b][sperm[j]][w];
    }
    __syncthreads();
    for (int idx = threadIdx.x; idx < K * K; idx += blockDim.x) {
        int i = idx / K, j = idx - i * K;
        int pi = (i < KC) ? sperm[i] : g_perm[b][i];
        const unsigned* ri = (i < KC) ? &srows[i][0] : &g_bitsA[b][pi][0];
        const unsigned* rj;
        if (j < KC) rj = &srows[j][0];
        else        rj = &g_bitsA[b][g_perm[b][j]][0];
        int s = 0;
        #pragma unroll
        for (int w = 0; w < W; ++w) s += __popc(ri[w] & rj[w]);
        s += (rj[pi >> 5] >> (pi & 31)) & 1;   // diagonal self-term of (A+I)@A
        out_a[((size_t)b * N + i) * N + j] = (float)s;
    }
}

// ---------------- launch ----------------------------------------------------
extern "C" void kernel_launch(void* const* d_in, const int* in_sizes, int n_in,
                              void* d_out, int out_size) {
    const float *x = nullptr, *adj = nullptr, *pos = nullptr, *order = nullptr;
    for (int i = 0; i < n_in; ++i) {
        if      (in_sizes[i] == B * N * N) adj   = (const float*)d_in[i];
        else if (in_sizes[i] == B * N * F) x     = (const float*)d_in[i];
        else if (in_sizes[i] == B * N * 3) pos   = (const float*)d_in[i];
        else if (in_sizes[i] == B * N) { if (!order) order = (const float*)d_in[i]; }
    }
    float* out = (float*)d_out;

    pack_zero_kernel<<<TOTAL_BLKS, 256>>>(adj, out);
    rank_kernel     <<<B * 8, 128>>>(order);
    inc_kernel      <<<(B * N) / 8, 256>>>();
    select_kernel   <<<B, 32>>>(out + OFF_M);
    {
        dim3 g(N, B);
        xp_kernel<<<g, F>>>(x, pos, out + OFF_X, out + OFF_P);
    }
    a_kernel<<<B, 1024>>>(out + OFF_A);
}

// round 6
// speedup vs baseline: 2.4904x; 2.4904x over previous
#include <cuda_runtime.h>
#include <cstdint>

#define B 4
#define N 1024
#define F 256
#define W 32            // 32 x u32 words per 1024-bit row
#define FULL 0xFFFFFFFFu

#define PACK_BLKS 512   // 512 blocks * 8 warps = 4096 rows
#define TOTAL_BLKS 2048 // extra 1536 blocks do the zero-fill
#define MAXK 344        // smem row-cache capacity in a_kernel (guarded fallback)
#define MAXL 128        // neighbor-list capacity in xp_kernel

// ---------------- scratch (device globals; no allocations allowed) ----------
__device__ unsigned g_bitsA [B][N][W];   // adj rows as bitmasks (node space)
__device__ unsigned g_bits1 [B][N][W];   // (adj + I) rows as bitmasks (node space)
__device__ uint2    g_excR  [B][N][W];   // rank-space rows: row r, cols by rank {exc,inc}
__device__ int      g_rank  [B][N];      // stable sorted position of order[b][i]
__device__ int      g_inv   [B][N];      // inverse permutation: rank -> node
__device__ int      g_perm  [B][N];      // top_k permutation (stable)
__device__ int      g_K     [B];         // number of selected nodes

// Output layout (float32, concatenated):
#define OFF_X   0
#define OFF_P   (B*N*F)
#define OFF_A   (B*N*F + B*N*3)
#define OFF_M   (B*N*F + B*N*3 + B*N*N)
#define NZERO4  ((B*N*F + B*N*3 + B*N*N) / 4)

// ---------------- K0: pack adj rows into bitmasks + zero-fill outputs -------
__global__ void pack_zero_kernel(const float* __restrict__ adj, float* __restrict__ out) {
    if (blockIdx.x >= PACK_BLKS) {
        int zb = blockIdx.x - PACK_BLKS;
        float4 z = make_float4(0.f, 0.f, 0.f, 0.f);
        float4* o = (float4*)out;
        for (int i = zb * blockDim.x + threadIdx.x; i < NZERO4;
             i += (TOTAL_BLKS - PACK_BLKS) * blockDim.x)
            o[i] = z;
        return;
    }
    int warp = (blockIdx.x * blockDim.x + threadIdx.x) >> 5;   // 0..4095
    int lane = threadIdx.x & 31;
    int b = warp >> 10, i = warp & (N - 1);
    const float4* r4 = (const float4*)(adj + ((size_t)b * N + i) * N) + lane * 8;
    unsigned w = 0;
    #pragma unroll
    for (int j = 0; j < 8; ++j) {
        float4 v = r4[j];
        w |= (v.x != 0.f ? 1u : 0u) << (4 * j)
           | (v.y != 0.f ? 1u : 0u) << (4 * j + 1)
           | (v.z != 0.f ? 1u : 0u) << (4 * j + 2)
           | (v.w != 0.f ? 1u : 0u) << (4 * j + 3);
    }
    g_bitsA[b][i][lane] = w;
    unsigned m1 = w | ((lane == (i >> 5)) ? (1u << (i & 31)) : 0u);
    g_bits1[b][i][lane] = m1;
}

// ---------------- K1: stable rank of each node by order value ---------------
__global__ void rank_kernel(const float* __restrict__ order) {
    int b = blockIdx.x >> 3;
    int i = (blockIdx.x & 7) * 128 + threadIdx.x;
    __shared__ float so[N];
    for (int j = threadIdx.x; j < N; j += 128) so[j] = order[b * N + j];
    __syncthreads();
    float oi = so[i];
    int r = 0;
    const float4* s4 = (const float4*)so;
    #pragma unroll 8
    for (int j4 = 0; j4 < N / 4; ++j4) {
        float4 v = s4[j4];
        int j = j4 * 4;
        r += (v.x < oi) || (v.x == oi && (j + 0) < i);
        r += (v.y < oi) || (v.y == oi && (j + 1) < i);
        r += (v.z < oi) || (v.z == oi && (j + 2) < i);
        r += (v.w < oi) || (v.w == oi && (j + 3) < i);
    }
    g_rank[b][i] = r;
    g_inv[b][r] = i;
}

// ---------------- K2: inc rows + permute {exc,inc} into RANK space ----------
// Row for node i goes to row rank[i]; column bit t of lane = rank lane*32+t,
// sourced from node bit inv[lane*32+t] via warp shfl.
__global__ void inc_perm_kernel() {
    int warp = (blockIdx.x * blockDim.x + threadIdx.x) >> 5;
    int lane = threadIdx.x & 31;
    int b = warp >> 10, i = warp & (N - 1);
    unsigned exc = g_bits1[b][i][lane];
    unsigned acc = 0;
    #pragma unroll 4
    for (int w = 0; w < W; ++w) {
        unsigned word = __shfl_sync(FULL, exc, w);
        while (word) {
            int bit = __ffs(word) - 1;
            word &= word - 1;
            acc |= g_bitsA[b][w * 32 + bit][lane];
        }
    }
    // column permutation to rank space
    int sj[32];
    const int4* inv4 = (const int4*)&g_inv[b][0];
    #pragma unroll
    for (int q = 0; q < 8; ++q) {
        int4 v = inv4[lane * 8 + q];
        sj[4 * q] = v.x; sj[4 * q + 1] = v.y; sj[4 * q + 2] = v.z; sj[4 * q + 3] = v.w;
    }
    unsigned excw = 0, incw = 0;
    #pragma unroll
    for (int t = 0; t < 32; ++t) {
        int j = sj[t];
        unsigned ew = __shfl_sync(FULL, exc, j >> 5);
        unsigned iw = __shfl_sync(FULL, acc, j >> 5);
        excw |= ((ew >> (j & 31)) & 1u) << t;
        incw |= ((iw >> (j & 31)) & 1u) << t;
    }
    int r = g_rank[b][i];
    g_excR[b][r][lane] = make_uint2(excw, incw);
}

// ---------------- K3: serial greedy selection, rank space (1 warp/batch) ----
__global__ void select_kernel(float* __restrict__ out_mask) {
    int b = blockIdx.x;
    int lane = threadIdx.x;
    __shared__ int sinv[N];
    __shared__ unsigned snode[W];
    #pragma unroll
    for (int w = 0; w < W; ++w) sinv[w * 32 + lane] = g_inv[b][w * 32 + lane];
    snode[lane] = 0;
    __syncwarp();

    unsigned av = FULL;                       // node_mask all-true
    unsigned sel = 0;                         // rank-space selected set
    unsigned fr = (lane == 0) ? 1u : 0u;      // initial frontier = rank 0
    int r = 0;                                // current rank (argmin over all)

    int guard = 0;
    while (guard++ < 2 * N) {
        unsigned cur = (lane == (r >> 5)) ? (1u << (r & 31)) : 0u;
        sel |= cur;
        uint2 eg = g_excR[b][r][lane];        // one coalesced LDG.64
        av &= ~cur & ~eg.x;
        fr = (fr | eg.y) & av;
        unsigned bal = __ballot_sync(FULL, fr != 0u);
        if (!bal) {                           // frontier died -> restart on av
            fr = av;
            bal = __ballot_sync(FULL, av != 0u);
            if (!bal) break;                  // done
        }
        int lead = __ffs(bal) - 1;
        unsigned wrd = __shfl_sync(FULL, fr, lead);
        r = lead * 32 + (__ffs(wrd) - 1);     // min rank in frontier
    }

    // convert rank-space sel to node space (≈K bits total; cheap)
    unsigned m = sel;
    while (m) {
        int t = __ffs(m) - 1;
        m &= m - 1;
        int node = sinv[lane * 32 + t];
        atomicOr(&snode[node >> 5], 1u << (node & 31));
    }
    __syncwarp();
    unsigned selN = snode[lane];

    // stable top_k permutation: selected ascending, then unselected ascending
    int cnt = __popc(selN);
    int v = cnt;
    #pragma unroll
    for (int o = 1; o < 32; o <<= 1) {
        int n2 = __shfl_up_sync(FULL, v, o);
        if (lane >= o) v += n2;
    }
    int K = __shfl_sync(FULL, v, 31);
    int selpos = v - cnt;
    int unspos = K + (lane * 32 - selpos);
    #pragma unroll
    for (int i = 0; i < 32; ++i) {
        int node = lane * 32 + i;
        if ((selN >> i) & 1u) g_perm[b][selpos++] = node;
        else                  g_perm[b][unspos++] = node;
    }
    if (lane == 0) g_K[b] = K;
    #pragma unroll
    for (int w = 0; w < W; ++w) {
        int j = w * 32 + lane;
        out_mask[b * N + j] = (j < K) ? 1.0f : 0.0f;
    }
}

// ---------------- K4: pooled features x_p and pos_p (live rows only) --------
__global__ void xp_kernel(const float* __restrict__ x, const float* __restrict__ pos,
                          float* __restrict__ out_x, float* __restrict__ out_pos) {
    int b = blockIdx.y, k = blockIdx.x;
    if (k >= g_K[b]) return;                   // padding already zero-filled
    int f = threadIdx.x;                       // 256 threads == F
    __shared__ int spk, snn;
    __shared__ int list[MAXL];
    if (f == 0) spk = g_perm[b][k];
    __syncthreads();
    if (f < 32) {
        unsigned wd = g_bits1[b][spk][f];
        int c = __popc(wd);
        int v = c;
        #pragma unroll
        for (int o = 1; o < 32; o <<= 1) {
            int t = __shfl_up_sync(FULL, v, o);
            if (f >= o) v += t;
        }
        int p = v - c;
        while (wd) {
            int bt = __ffs(wd) - 1;
            wd &= wd - 1;
            list[p++] = f * 32 + bt;
        }
        if (f == 31) snn = v;
    }
    __syncthreads();
    int nn = snn;

    float acc = 0.0f;
    #pragma unroll 4
    for (int i = 0; i < nn; ++i)
        acc += x[((size_t)b * N + list[i]) * F + f];
    out_x[((size_t)b * N + k) * F + f] = acc;

    if (f < 3) {
        float p = 0.0f;
        for (int i = 0; i < nn; ++i)
            p += pos[((size_t)b * N + list[i]) * 3 + f];
        out_pos[((size_t)b * N + k) * 3 + f] = p / (float)nn;
    }
}

// ---------------- K5: coarsened adjacency, one block per batch --------------
__global__ void a_kernel(float* __restrict__ out_a) {
    int b = blockIdx.x;
    int K = g_K[b];
    __shared__ unsigned srows[MAXK][33];
    __shared__ int sperm[MAXK];
    int KC = K < MAXK ? K : MAXK;
    for (int j = threadIdx.x; j < KC; j += blockDim.x) sperm[j] = g_perm[b][j];
    __syncthreads();
    for (int t = threadIdx.x; t < KC * W; t += blockDim.x) {
        int j = t >> 5, w = t & 31;
        srows[j][w] = g_bitsA[b][sperm[j]][w];
    }
    __syncthreads();
    for (int idx = threadIdx.x; idx < K * K; idx += blockDim.x) {
        int i = idx / K, j = idx - i * K;
        int pi = (i < KC) ? sperm[i] : g_perm[b][i];
        const unsigned* ri = (i < KC) ? &srows[i][0] : &g_bitsA[b][pi][0];
        const unsigned* rj;
        if (j < KC) rj = &srows[j][0];
        else        rj = &g_bitsA[b][g_perm[b][j]][0];
        int s = 0;
        #pragma unroll
        for (int w = 0; w < W; ++w) s += __popc(ri[w] & rj[w]);
        s += (rj[pi >> 5] >> (pi & 31)) & 1;   // diagonal self-term of (A+I)@A
        out_a[((size_t)b * N + i) * N + j] = (float)s;
    }
}

// ---------------- launch ----------------------------------------------------
extern "C" void kernel_launch(void* const* d_in, const int* in_sizes, int n_in,
                              void* d_out, int out_size) {
    const float *x = nullptr, *adj = nullptr, *pos = nullptr, *order = nullptr;
    for (int i = 0; i < n_in; ++i) {
        if      (in_sizes[i] == B * N * N) adj   = (const float*)d_in[i];
        else if (in_sizes[i] == B * N * F) x     = (const float*)d_in[i];
        else if (in_sizes[i] == B * N * 3) pos   = (const float*)d_in[i];
        else if (in_sizes[i] == B * N) { if (!order) order = (const float*)d_in[i]; }
    }
    float* out = (float*)d_out;

    pack_zero_kernel<<<TOTAL_BLKS, 256>>>(adj, out);
    rank_kernel     <<<B * 8, 128>>>(order);
    inc_perm_kernel <<<(B * N) / 8, 256>>>();
    select_kernel   <<<B, 32>>>(out + OFF_M);
    {
        dim3 g(N, B);
        xp_kernel<<<g, F>>>(x, pos, out + OFF_X, out + OFF_P);
    }
    a_kernel<<<B, 1024>>>(out + OFF_A);
}